// round 4
// baseline (speedup 1.0000x reference)
#include <cuda_runtime.h>

#define N_NODES 50000
#define IN_DIM  128
#define OUT_DIM 256
#define N_EDGES 800000
#define SCAN_BLK 256
#define NBLK_SCAN ((N_NODES + SCAN_BLK - 1) / SCAN_BLK)   // 196

// Scratch (__device__ globals; allocation APIs are forbidden)
__device__ float g_agg[(size_t)N_NODES * IN_DIM];   // 25.6 MB
__device__ float g_dinv[N_NODES];
__device__ int   g_cnt[N_NODES];
__device__ int   g_off[N_NODES];
__device__ int   g_cur[N_NODES];
__device__ int   g_csr[N_EDGES];
__device__ int   g_bsum[NBLK_SCAN];
__device__ int   g_boff[NBLK_SCAN];
__device__ int   g_is32;

__device__ __forceinline__ int clamp_node(int v) {
    v = v < 0 ? 0 : v;
    return v > (N_NODES - 1) ? (N_NODES - 1) : v;
}

// Read edge e as (src,dst) under either int64 or int32 encoding, clamped.
__device__ __forceinline__ void load_edge(const void* __restrict__ ei, int e,
                                          int& s, int& d) {
    if (g_is32) {
        const int* p = (const int*)ei;
        s = p[2 * e];
        d = p[2 * e + 1];
    } else {
        const long long* p = (const long long*)ei;
        s = (int)p[2 * e];
        d = (int)p[2 * e + 1];
    }
    s = clamp_node(s);
    d = clamp_node(d);
}

// ---------------------------------------------------------------------------
// Probe: decide int32 vs int64 encoding of edge_index.
// If any of the first 1024 int64 words is outside [0, N_NODES), it's int32.
// (1024 words are in-bounds under both interpretations.)
// ---------------------------------------------------------------------------
__global__ void k_probe(const long long* __restrict__ ei) {
    __shared__ int bad[256];
    int t = threadIdx.x;
    int local = 0;
    for (int i = t; i < 1024; i += 256) {
        long long v = ei[i];
        if (v < 0 || v >= (long long)N_NODES) local = 1;
    }
    bad[t] = local;
    __syncthreads();
    for (int off = 128; off > 0; off >>= 1) {
        if (t < off) bad[t] |= bad[t + off];
        __syncthreads();
    }
    if (t == 0) g_is32 = bad[0];
}

// ---------------------------------------------------------------------------
__global__ void k_init(const void* __restrict__ ei_unused) {
    int i = blockIdx.x * blockDim.x + threadIdx.x;
    if (i < N_NODES) g_cnt[i] = 0;
    (void)ei_unused;
}

__global__ void k_count(const void* __restrict__ ei) {
    int e = blockIdx.x * blockDim.x + threadIdx.x;
    if (e < N_EDGES) {
        int s, d;
        load_edge(ei, e, s, d);
        atomicAdd(&g_cnt[d], 1);
    }
}

// Two-level exclusive scan of g_cnt (256-thread blocks).
__global__ void k_scan1(const void* __restrict__ ei_unused) {
    __shared__ int sh[SCAN_BLK];
    int t = threadIdx.x;
    int i = blockIdx.x * SCAN_BLK + t;
    int v = (i < N_NODES) ? g_cnt[i] : 0;
    sh[t] = v;
    __syncthreads();
    for (int off = 1; off < SCAN_BLK; off <<= 1) {
        int add = (t >= off) ? sh[t - off] : 0;
        __syncthreads();
        sh[t] += add;
        __syncthreads();
    }
    int incl = sh[t];
    if (i < N_NODES) g_off[i] = incl - v;
    if (t == SCAN_BLK - 1) g_bsum[blockIdx.x] = incl;
    (void)ei_unused;
}

__global__ void k_scan2(const void* __restrict__ ei_unused) {
    __shared__ int sh[SCAN_BLK];
    int t = threadIdx.x;
    int v = (t < NBLK_SCAN) ? g_bsum[t] : 0;
    sh[t] = v;
    __syncthreads();
    for (int off = 1; off < SCAN_BLK; off <<= 1) {
        int add = (t >= off) ? sh[t - off] : 0;
        __syncthreads();
        sh[t] += add;
        __syncthreads();
    }
    if (t < NBLK_SCAN) g_boff[t] = sh[t] - v;
    (void)ei_unused;
}

__global__ void k_scan3(const void* __restrict__ ei_unused) {
    int i = blockIdx.x * blockDim.x + threadIdx.x;
    if (i < N_NODES) {
        int o = g_off[i] + g_boff[i / SCAN_BLK];
        g_off[i] = o;
        g_cur[i] = o;
        g_dinv[i] = rsqrtf((float)(g_cnt[i] + 1));   // +1 self loop
    }
    (void)ei_unused;
}

__global__ void k_fill(const void* __restrict__ ei) {
    int e = blockIdx.x * blockDim.x + threadIdx.x;
    if (e < N_EDGES) {
        int s, d;
        load_edge(ei, e, s, d);
        int pos = atomicAdd(&g_cur[d], 1);
        pos = pos < 0 ? 0 : (pos > N_EDGES - 1 ? N_EDGES - 1 : pos);
        g_csr[pos] = s;
    }
}

// ---------------------------------------------------------------------------
// Gather: agg[d] = dinv[d] * ( dinv[d]*x[d] + sum_{s in N(d)} dinv[s]*x[s] )
// One block (128 threads) per node; thread t owns feature column t.
// ---------------------------------------------------------------------------
__global__ void k_gather(const float* __restrict__ x) {
    int d = blockIdx.x;
    int t = threadIdx.x;
    float dd = g_dinv[d];
    float acc = dd * x[(size_t)d * IN_DIM + t];
    int start = g_off[d];
    int end   = start + g_cnt[d];
    for (int e = start; e < end; e++) {
        int s = g_csr[e];
        acc += g_dinv[s] * x[(size_t)s * IN_DIM + t];
    }
    g_agg[(size_t)d * IN_DIM + t] = dd * acc;
}

// ---------------------------------------------------------------------------
// GEMM: out = relu(agg @ W^T + b).  64x64 tile / 256 threads / 4x4 reg tile.
// Scalar loads/stores; shared padded to 65 columns.
// ---------------------------------------------------------------------------
__global__ void k_gemm(const float* __restrict__ W,
                       const float* __restrict__ b,
                       float* __restrict__ out) {
    __shared__ float As[16][65];
    __shared__ float Bs[16][65];

    const int tid = threadIdx.x;
    const int tx  = tid & 15;
    const int ty  = tid >> 4;
    const int rowBase = blockIdx.x * 64;
    const int colBase = blockIdx.y * 64;

    float acc00 = 0.f, acc01 = 0.f, acc02 = 0.f, acc03 = 0.f;
    float acc10 = 0.f, acc11 = 0.f, acc12 = 0.f, acc13 = 0.f;
    float acc20 = 0.f, acc21 = 0.f, acc22 = 0.f, acc23 = 0.f;
    float acc30 = 0.f, acc31 = 0.f, acc32 = 0.f, acc33 = 0.f;

    for (int k0 = 0; k0 < IN_DIM; k0 += 16) {
        for (int idx = tid; idx < 64 * 16; idx += 256) {
            int r  = idx >> 4;
            int kk = idx & 15;
            int gr = rowBase + r;
            float av = 0.f;
            if (gr < N_NODES) av = g_agg[(size_t)gr * IN_DIM + k0 + kk];
            As[kk][r] = av;
            int gc = colBase + r;
            Bs[kk][r] = W[(size_t)gc * IN_DIM + k0 + kk];
        }
        __syncthreads();

        #pragma unroll
        for (int k = 0; k < 16; k++) {
            float a0 = As[k][ty * 4 + 0];
            float a1 = As[k][ty * 4 + 1];
            float a2 = As[k][ty * 4 + 2];
            float a3 = As[k][ty * 4 + 3];
            float b0 = Bs[k][tx * 4 + 0];
            float b1 = Bs[k][tx * 4 + 1];
            float b2 = Bs[k][tx * 4 + 2];
            float b3 = Bs[k][tx * 4 + 3];
            acc00 += a0 * b0; acc01 += a0 * b1; acc02 += a0 * b2; acc03 += a0 * b3;
            acc10 += a1 * b0; acc11 += a1 * b1; acc12 += a1 * b2; acc13 += a1 * b3;
            acc20 += a2 * b0; acc21 += a2 * b1; acc22 += a2 * b2; acc23 += a2 * b3;
            acc30 += a3 * b0; acc31 += a3 * b1; acc32 += a3 * b2; acc33 += a3 * b3;
        }
        __syncthreads();
    }

    int c = colBase + tx * 4;
    float b0 = b[c + 0], b1 = b[c + 1], b2 = b[c + 2], b3 = b[c + 3];

    int r0 = rowBase + ty * 4;
    if (r0 + 0 < N_NODES) {
        float* o = &out[(size_t)(r0 + 0) * OUT_DIM + c];
        o[0] = fmaxf(acc00 + b0, 0.f); o[1] = fmaxf(acc01 + b1, 0.f);
        o[2] = fmaxf(acc02 + b2, 0.f); o[3] = fmaxf(acc03 + b3, 0.f);
    }
    if (r0 + 1 < N_NODES) {
        float* o = &out[(size_t)(r0 + 1) * OUT_DIM + c];
        o[0] = fmaxf(acc10 + b0, 0.f); o[1] = fmaxf(acc11 + b1, 0.f);
        o[2] = fmaxf(acc12 + b2, 0.f); o[3] = fmaxf(acc13 + b3, 0.f);
    }
    if (r0 + 2 < N_NODES) {
        float* o = &out[(size_t)(r0 + 2) * OUT_DIM + c];
        o[0] = fmaxf(acc20 + b0, 0.f); o[1] = fmaxf(acc21 + b1, 0.f);
        o[2] = fmaxf(acc22 + b2, 0.f); o[3] = fmaxf(acc23 + b3, 0.f);
    }
    if (r0 + 3 < N_NODES) {
        float* o = &out[(size_t)(r0 + 3) * OUT_DIM + c];
        o[0] = fmaxf(acc30 + b0, 0.f); o[1] = fmaxf(acc31 + b1, 0.f);
        o[2] = fmaxf(acc32 + b2, 0.f); o[3] = fmaxf(acc33 + b3, 0.f);
    }
}

// ---------------------------------------------------------------------------
extern "C" void kernel_launch(void* const* d_in, const int* in_sizes, int n_in,
                              void* d_out, int out_size) {
    const float* x   = (const float*)d_in[0];
    const void*  ei  = d_in[1];
    const float* W   = (const float*)d_in[2];
    const float* b   = (const float*)d_in[3];
    float*       out = (float*)d_out;

    k_probe<<<1, 256>>>((const long long*)ei);
    k_init <<<(N_NODES + 255) / 256, 256>>>(ei);
    k_count<<<(N_EDGES + 255) / 256, 256>>>(ei);
    k_scan1<<<NBLK_SCAN, SCAN_BLK>>>(ei);
    k_scan2<<<1, SCAN_BLK>>>(ei);
    k_scan3<<<(N_NODES + 255) / 256, 256>>>(ei);
    k_fill <<<(N_EDGES + 255) / 256, 256>>>(ei);

    k_gather<<<N_NODES, IN_DIM>>>(x);

    dim3 ggrid((N_NODES + 63) / 64, OUT_DIM / 64);
    k_gemm<<<ggrid, 256>>>(W, b, out);
}

// round 5
// speedup vs baseline: 1.7888x; 1.7888x over previous
#include <cuda_runtime.h>
#include <cstdint>

#define N_NODES 50000
#define IN_DIM  128
#define OUT_DIM 256
#define N_EDGES 800000
#define SCAN_BLK 256
#define NBLK_SCAN ((N_NODES + SCAN_BLK - 1) / SCAN_BLK)   // 196

// Scratch (__device__ globals; allocation APIs are forbidden)
__device__ float g_agg[(size_t)N_NODES * IN_DIM];   // 25.6 MB
__device__ float g_dinv[N_NODES];
__device__ int   g_cnt[N_NODES];
__device__ int   g_off[N_NODES];
__device__ int   g_cur[N_NODES];
__device__ int   g_csr[N_EDGES];
__device__ int   g_bsum[NBLK_SCAN];
__device__ int   g_boff[NBLK_SCAN];
__device__ int   g_is32;

__device__ __forceinline__ int clamp_node(int v) {
    v = v < 0 ? 0 : v;
    return v > (N_NODES - 1) ? (N_NODES - 1) : v;
}

__device__ __forceinline__ void load_edge(const void* __restrict__ ei, int e,
                                          int& s, int& d) {
    if (g_is32) {
        const int* p = (const int*)ei;
        s = p[2 * e];
        d = p[2 * e + 1];
    } else {
        const long long* p = (const long long*)ei;
        s = (int)p[2 * e];
        d = (int)p[2 * e + 1];
    }
    s = clamp_node(s);
    d = clamp_node(d);
}

// ---------------------------------------------------------------------------
// init counters; block 0 additionally probes int32-vs-int64 encoding.
// An int32 pair read as int64 is s + d*2^32 -> out of [0,N) unless d==0;
// 1024 consecutive such words valid is impossible for random edges.
// ---------------------------------------------------------------------------
__global__ void k_init(const long long* __restrict__ ei) {
    int i = blockIdx.x * blockDim.x + threadIdx.x;
    if (i < N_NODES) g_cnt[i] = 0;
    if (blockIdx.x == 0) {
        __shared__ int bad[256];
        int t = threadIdx.x;
        int local = 0;
        for (int k = t; k < 1024; k += 256) {
            long long v = ei[k];
            if (v < 0 || v >= (long long)N_NODES) local = 1;
        }
        bad[t] = local;
        __syncthreads();
        for (int off = 128; off > 0; off >>= 1) {
            if (t < off) bad[t] |= bad[t + off];
            __syncthreads();
        }
        if (t == 0) g_is32 = bad[0];
    }
}

__global__ void k_count(const void* __restrict__ ei) {
    int e = blockIdx.x * blockDim.x + threadIdx.x;
    if (e < N_EDGES) {
        int s, d;
        load_edge(ei, e, s, d);
        atomicAdd(&g_cnt[d], 1);
    }
}

// Two-level exclusive scan of g_cnt.
__global__ void k_scan1() {
    __shared__ int sh[SCAN_BLK];
    int t = threadIdx.x;
    int i = blockIdx.x * SCAN_BLK + t;
    int v = (i < N_NODES) ? g_cnt[i] : 0;
    sh[t] = v;
    __syncthreads();
    for (int off = 1; off < SCAN_BLK; off <<= 1) {
        int add = (t >= off) ? sh[t - off] : 0;
        __syncthreads();
        sh[t] += add;
        __syncthreads();
    }
    int incl = sh[t];
    if (i < N_NODES) g_off[i] = incl - v;
    if (t == SCAN_BLK - 1) g_bsum[blockIdx.x] = incl;
}

__global__ void k_scan2() {
    __shared__ int sh[SCAN_BLK];
    int t = threadIdx.x;
    int v = (t < NBLK_SCAN) ? g_bsum[t] : 0;
    sh[t] = v;
    __syncthreads();
    for (int off = 1; off < SCAN_BLK; off <<= 1) {
        int add = (t >= off) ? sh[t - off] : 0;
        __syncthreads();
        sh[t] += add;
        __syncthreads();
    }
    if (t < NBLK_SCAN) g_boff[t] = sh[t] - v;
}

__global__ void k_scan3() {
    int i = blockIdx.x * blockDim.x + threadIdx.x;
    if (i < N_NODES) {
        int o = g_off[i] + g_boff[i / SCAN_BLK];
        g_off[i] = o;
        g_cur[i] = o;
        g_dinv[i] = rsqrtf((float)(g_cnt[i] + 1));   // +1 self loop
    }
}

__global__ void k_fill(const void* __restrict__ ei) {
    int e = blockIdx.x * blockDim.x + threadIdx.x;
    if (e < N_EDGES) {
        int s, d;
        load_edge(ei, e, s, d);
        int pos = atomicAdd(&g_cur[d], 1);
        pos = pos < 0 ? 0 : (pos > N_EDGES - 1 ? N_EDGES - 1 : pos);
        g_csr[pos] = s;
    }
}

// ---------------------------------------------------------------------------
// Gather: agg[d] = dinv[d] * ( dinv[d]*x[d] + sum_{s in N(d)} dinv[s]*x[s] )
// One warp per node; lane owns one float4 (4 feature columns).
// ---------------------------------------------------------------------------
__global__ __launch_bounds__(256) void k_gather(const float* __restrict__ x) {
    int d    = (blockIdx.x * blockDim.x + threadIdx.x) >> 5;
    int lane = threadIdx.x & 31;
    if (d >= N_NODES) return;

    const float4* xr = (const float4*)x;
    float dd = g_dinv[d];
    float4 v = xr[(size_t)d * 32 + lane];
    float4 acc = make_float4(dd * v.x, dd * v.y, dd * v.z, dd * v.w);

    int start = g_off[d];
    int end   = start + g_cnt[d];
    for (int e = start; e < end; e++) {
        int   s = g_csr[e];                 // uniform -> broadcast
        float w = g_dinv[s];
        float4 xv = xr[(size_t)s * 32 + lane];
        acc.x += w * xv.x;
        acc.y += w * xv.y;
        acc.z += w * xv.z;
        acc.w += w * xv.w;
    }
    acc.x *= dd; acc.y *= dd; acc.z *= dd; acc.w *= dd;
    ((float4*)g_agg)[(size_t)d * 32 + lane] = acc;
}

// ---------------------------------------------------------------------------
// GEMM: out = relu(agg @ W^T + b)
// 128x128 tile / 256 threads / 8x8 microtile / packed fma.rn.f32x2.
// acc pairs over the M dimension: acc[p][j] = (row_even, row_odd) x col j.
// ---------------------------------------------------------------------------
#define BM 128
#define BK 16
#define SA 132   // padded row stride (floats); 16B-aligned rows

__global__ __launch_bounds__(256, 2) void k_gemm(const float* __restrict__ W,
                                                 const float* __restrict__ bia,
                                                 float* __restrict__ out) {
    __shared__ float As[BK][SA];
    __shared__ float Bs[BK][SA];

    const int tid = threadIdx.x;
    const int tx  = tid & 15;        // col group
    const int ty  = tid >> 4;        // row group
    const int rowBase = blockIdx.x * BM;
    const int colBase = blockIdx.y * BM;

    unsigned long long acc[4][8];
    #pragma unroll
    for (int i = 0; i < 4; i++)
        #pragma unroll
        for (int j = 0; j < 8; j++) acc[i][j] = 0ull;

    for (int k0 = 0; k0 < IN_DIM; k0 += BK) {
        #pragma unroll
        for (int i = 0; i < 2; i++) {
            int lin = tid + i * 256;
            int row = lin >> 2;          // 0..127
            int kq  = lin & 3;           // float4 index in k
            int gr  = rowBase + row;
            float4 va = make_float4(0.f, 0.f, 0.f, 0.f);
            if (gr < N_NODES)
                va = *(const float4*)&g_agg[(size_t)gr * IN_DIM + k0 + kq * 4];
            As[kq * 4 + 0][row] = va.x;
            As[kq * 4 + 1][row] = va.y;
            As[kq * 4 + 2][row] = va.z;
            As[kq * 4 + 3][row] = va.w;

            int gc = colBase + row;      // OUT_DIM=256, grid.y=2 -> in range
            float4 vb = *(const float4*)&W[(size_t)gc * IN_DIM + k0 + kq * 4];
            Bs[kq * 4 + 0][row] = vb.x;
            Bs[kq * 4 + 1][row] = vb.y;
            Bs[kq * 4 + 2][row] = vb.z;
            Bs[kq * 4 + 3][row] = vb.w;
        }
        __syncthreads();

        #pragma unroll
        for (int k = 0; k < BK; k++) {
            float4 a0 = *(const float4*)&As[k][ty * 4];
            float4 a1 = *(const float4*)&As[k][64 + ty * 4];
            float4 b0 = *(const float4*)&Bs[k][tx * 4];
            float4 b1 = *(const float4*)&Bs[k][64 + tx * 4];

            unsigned long long ap[4], bp[8];
            asm("mov.b64 %0, {%1,%2};" : "=l"(ap[0]) : "f"(a0.x), "f"(a0.y));
            asm("mov.b64 %0, {%1,%2};" : "=l"(ap[1]) : "f"(a0.z), "f"(a0.w));
            asm("mov.b64 %0, {%1,%2};" : "=l"(ap[2]) : "f"(a1.x), "f"(a1.y));
            asm("mov.b64 %0, {%1,%2};" : "=l"(ap[3]) : "f"(a1.z), "f"(a1.w));
            asm("mov.b64 %0, {%1,%1};" : "=l"(bp[0]) : "f"(b0.x));
            asm("mov.b64 %0, {%1,%1};" : "=l"(bp[1]) : "f"(b0.y));
            asm("mov.b64 %0, {%1,%1};" : "=l"(bp[2]) : "f"(b0.z));
            asm("mov.b64 %0, {%1,%1};" : "=l"(bp[3]) : "f"(b0.w));
            asm("mov.b64 %0, {%1,%1};" : "=l"(bp[4]) : "f"(b1.x));
            asm("mov.b64 %0, {%1,%1};" : "=l"(bp[5]) : "f"(b1.y));
            asm("mov.b64 %0, {%1,%1};" : "=l"(bp[6]) : "f"(b1.z));
            asm("mov.b64 %0, {%1,%1};" : "=l"(bp[7]) : "f"(b1.w));

            #pragma unroll
            for (int p = 0; p < 4; p++)
                #pragma unroll
                for (int j = 0; j < 8; j++)
                    asm("fma.rn.f32x2 %0, %1, %2, %0;"
                        : "+l"(acc[p][j]) : "l"(ap[p]), "l"(bp[j]));
        }
        __syncthreads();
    }

    // Epilogue
    int c0 = colBase + tx * 4;
    int c1 = colBase + 64 + tx * 4;
    float4 bb0 = *(const float4*)&bia[c0];
    float4 bb1 = *(const float4*)&bia[c1];

    #pragma unroll
    for (int p = 0; p < 4; p++) {
        int rbase = rowBase + ((p < 2) ? (ty * 4) : (64 + ty * 4)) + (p & 1) * 2;
        float lo[8], hi[8];
        #pragma unroll
        for (int j = 0; j < 8; j++)
            asm("mov.b64 {%0,%1}, %2;" : "=f"(lo[j]), "=f"(hi[j]) : "l"(acc[p][j]));

        if (rbase < N_NODES) {
            float4 o0 = make_float4(fmaxf(lo[0] + bb0.x, 0.f), fmaxf(lo[1] + bb0.y, 0.f),
                                    fmaxf(lo[2] + bb0.z, 0.f), fmaxf(lo[3] + bb0.w, 0.f));
            float4 o1 = make_float4(fmaxf(lo[4] + bb1.x, 0.f), fmaxf(lo[5] + bb1.y, 0.f),
                                    fmaxf(lo[6] + bb1.z, 0.f), fmaxf(lo[7] + bb1.w, 0.f));
            *(float4*)&out[(size_t)rbase * OUT_DIM + c0] = o0;
            *(float4*)&out[(size_t)rbase * OUT_DIM + c1] = o1;
        }
        if (rbase + 1 < N_NODES) {
            float4 o0 = make_float4(fmaxf(hi[0] + bb0.x, 0.f), fmaxf(hi[1] + bb0.y, 0.f),
                                    fmaxf(hi[2] + bb0.z, 0.f), fmaxf(hi[3] + bb0.w, 0.f));
            float4 o1 = make_float4(fmaxf(hi[4] + bb1.x, 0.f), fmaxf(hi[5] + bb1.y, 0.f),
                                    fmaxf(hi[6] + bb1.z, 0.f), fmaxf(hi[7] + bb1.w, 0.f));
            *(float4*)&out[(size_t)(rbase + 1) * OUT_DIM + c0] = o0;
            *(float4*)&out[(size_t)(rbase + 1) * OUT_DIM + c1] = o1;
        }
    }
}

// ---------------------------------------------------------------------------
extern "C" void kernel_launch(void* const* d_in, const int* in_sizes, int n_in,
                              void* d_out, int out_size) {
    const float* x   = (const float*)d_in[0];
    const void*  ei  = d_in[1];
    const float* W   = (const float*)d_in[2];
    const float* b   = (const float*)d_in[3];
    float*       out = (float*)d_out;

    k_init <<<(N_NODES + 255) / 256, 256>>>((const long long*)ei);
    k_count<<<(N_EDGES + 255) / 256, 256>>>(ei);
    k_scan1<<<NBLK_SCAN, SCAN_BLK>>>();
    k_scan2<<<1, SCAN_BLK>>>();
    k_scan3<<<(N_NODES + 255) / 256, 256>>>();
    k_fill <<<(N_EDGES + 255) / 256, 256>>>(ei);

    k_gather<<<(N_NODES * 32 + 255) / 256, 256>>>(x);

    dim3 ggrid((N_NODES + BM - 1) / BM, OUT_DIM / BM);
    k_gemm<<<ggrid, 256>>>(W, b, out);
}

// round 6
// speedup vs baseline: 1.8178x; 1.0163x over previous
#include <cuda_runtime.h>
#include <cstdint>

#define N_NODES 50000
#define IN_DIM  128
#define OUT_DIM 256
#define N_EDGES 800000
#define SCAN_BLK 256
#define NBLK_SCAN ((N_NODES + SCAN_BLK - 1) / SCAN_BLK)   // 196

// Scratch (__device__ globals; allocation APIs are forbidden)
__device__ float g_agg[(size_t)N_NODES * IN_DIM];   // 25.6 MB
__device__ float g_dinv[N_NODES];
__device__ int   g_cnt[N_NODES];
__device__ int   g_off[N_NODES];
__device__ int   g_cur[N_NODES];
__device__ int   g_csr[N_EDGES];
__device__ int   g_total;
__device__ int   g_is32;

__device__ __forceinline__ int clamp_node(int v) {
    v = v < 0 ? 0 : v;
    return v > (N_NODES - 1) ? (N_NODES - 1) : v;
}

__device__ __forceinline__ void load_edge(const void* __restrict__ ei, int e,
                                          int& s, int& d) {
    if (g_is32) {
        const int* p = (const int*)ei;
        s = p[2 * e];
        d = p[2 * e + 1];
    } else {
        const long long* p = (const long long*)ei;
        s = (int)p[2 * e];
        d = (int)p[2 * e + 1];
    }
    s = clamp_node(s);
    d = clamp_node(d);
}

// ---------------------------------------------------------------------------
// init: zero counters + global cursor; block 0 probes int32-vs-int64 encoding.
// ---------------------------------------------------------------------------
__global__ void k_init(const long long* __restrict__ ei) {
    int i = blockIdx.x * blockDim.x + threadIdx.x;
    if (i < N_NODES) g_cnt[i] = 0;
    if (i == 0) g_total = 0;
    if (blockIdx.x == 0) {
        __shared__ int bad[256];
        int t = threadIdx.x;
        int local = 0;
        for (int k = t; k < 1024; k += 256) {
            long long v = ei[k];
            if (v < 0 || v >= (long long)N_NODES) local = 1;
        }
        bad[t] = local;
        __syncthreads();
        for (int off = 128; off > 0; off >>= 1) {
            if (t < off) bad[t] |= bad[t + off];
            __syncthreads();
        }
        if (t == 0) g_is32 = bad[0];
    }
}

__global__ void k_count(const void* __restrict__ ei) {
    int e = blockIdx.x * blockDim.x + threadIdx.x;
    if (e < N_EDGES) {
        int s, d;
        load_edge(ei, e, s, d);
        atomicAdd(&g_cnt[d], 1);
    }
}

// ---------------------------------------------------------------------------
// One-kernel offsets: block-local exclusive scan + atomic block base.
// Segment order across blocks is arbitrary (atomic), which is fine: gather
// only needs each node's edges contiguous. Also emits cursors and dinv.
// ---------------------------------------------------------------------------
__global__ void k_scanA() {
    __shared__ int sh[SCAN_BLK];
    __shared__ int blockBase;
    int t = threadIdx.x;
    int i = blockIdx.x * SCAN_BLK + t;
    int v = (i < N_NODES) ? g_cnt[i] : 0;
    sh[t] = v;
    __syncthreads();
    for (int off = 1; off < SCAN_BLK; off <<= 1) {
        int add = (t >= off) ? sh[t - off] : 0;
        __syncthreads();
        sh[t] += add;
        __syncthreads();
    }
    if (t == SCAN_BLK - 1) blockBase = atomicAdd(&g_total, sh[SCAN_BLK - 1]);
    __syncthreads();
    if (i < N_NODES) {
        int o = blockBase + sh[t] - v;
        g_off[i] = o;
        g_cur[i] = o;
        g_dinv[i] = rsqrtf((float)(v + 1));   // +1 self loop
    }
}

__global__ void k_fill(const void* __restrict__ ei) {
    int e = blockIdx.x * blockDim.x + threadIdx.x;
    if (e < N_EDGES) {
        int s, d;
        load_edge(ei, e, s, d);
        int pos = atomicAdd(&g_cur[d], 1);
        pos = pos < 0 ? 0 : (pos > N_EDGES - 1 ? N_EDGES - 1 : pos);
        g_csr[pos] = s;
    }
}

// ---------------------------------------------------------------------------
// Gather: agg[d] = dinv[d] * ( dinv[d]*x[d] + sum_{s in N(d)} dinv[s]*x[s] )
// One warp per node; lane owns one float4. Unroll-by-4 with front-batched
// loads for MLP on the uniform (csr, dinv) chain.
// ---------------------------------------------------------------------------
__global__ __launch_bounds__(256) void k_gather(const float* __restrict__ x) {
    int d    = (blockIdx.x * blockDim.x + threadIdx.x) >> 5;
    int lane = threadIdx.x & 31;
    if (d >= N_NODES) return;

    const float4* xr = (const float4*)x;
    float dd = g_dinv[d];
    float4 v = xr[(size_t)d * 32 + lane];
    float4 acc = make_float4(dd * v.x, dd * v.y, dd * v.z, dd * v.w);

    int e   = g_off[d];
    int end = e + g_cnt[d];

    for (; e + 4 <= end; e += 4) {
        int s0 = g_csr[e + 0];
        int s1 = g_csr[e + 1];
        int s2 = g_csr[e + 2];
        int s3 = g_csr[e + 3];
        float w0 = g_dinv[s0];
        float w1 = g_dinv[s1];
        float w2 = g_dinv[s2];
        float w3 = g_dinv[s3];
        float4 x0 = xr[(size_t)s0 * 32 + lane];
        float4 x1 = xr[(size_t)s1 * 32 + lane];
        float4 x2 = xr[(size_t)s2 * 32 + lane];
        float4 x3 = xr[(size_t)s3 * 32 + lane];
        acc.x += w0 * x0.x; acc.y += w0 * x0.y; acc.z += w0 * x0.z; acc.w += w0 * x0.w;
        acc.x += w1 * x1.x; acc.y += w1 * x1.y; acc.z += w1 * x1.z; acc.w += w1 * x1.w;
        acc.x += w2 * x2.x; acc.y += w2 * x2.y; acc.z += w2 * x2.z; acc.w += w2 * x2.w;
        acc.x += w3 * x3.x; acc.y += w3 * x3.y; acc.z += w3 * x3.z; acc.w += w3 * x3.w;
    }
    for (; e < end; e++) {
        int   s = g_csr[e];
        float w = g_dinv[s];
        float4 xv = xr[(size_t)s * 32 + lane];
        acc.x += w * xv.x; acc.y += w * xv.y; acc.z += w * xv.z; acc.w += w * xv.w;
    }

    acc.x *= dd; acc.y *= dd; acc.z *= dd; acc.w *= dd;
    ((float4*)g_agg)[(size_t)d * 32 + lane] = acc;
}

// ---------------------------------------------------------------------------
// GEMM: out = relu(agg @ W^T + b)
// 128x128 tile / 256 threads / 8x8 microtile / packed fma.rn.f32x2.
// ---------------------------------------------------------------------------
#define BM 128
#define BK 16
#define SA 132

__global__ __launch_bounds__(256, 2) void k_gemm(const float* __restrict__ W,
                                                 const float* __restrict__ bia,
                                                 float* __restrict__ out) {
    __shared__ float As[BK][SA];
    __shared__ float Bs[BK][SA];

    const int tid = threadIdx.x;
    const int tx  = tid & 15;
    const int ty  = tid >> 4;
    const int rowBase = blockIdx.x * BM;
    const int colBase = blockIdx.y * BM;

    unsigned long long acc[4][8];
    #pragma unroll
    for (int i = 0; i < 4; i++)
        #pragma unroll
        for (int j = 0; j < 8; j++) acc[i][j] = 0ull;

    for (int k0 = 0; k0 < IN_DIM; k0 += BK) {
        #pragma unroll
        for (int i = 0; i < 2; i++) {
            int lin = tid + i * 256;
            int row = lin >> 2;
            int kq  = lin & 3;
            int gr  = rowBase + row;
            float4 va = make_float4(0.f, 0.f, 0.f, 0.f);
            if (gr < N_NODES)
                va = *(const float4*)&g_agg[(size_t)gr * IN_DIM + k0 + kq * 4];
            As[kq * 4 + 0][row] = va.x;
            As[kq * 4 + 1][row] = va.y;
            As[kq * 4 + 2][row] = va.z;
            As[kq * 4 + 3][row] = va.w;

            int gc = colBase + row;
            float4 vb = *(const float4*)&W[(size_t)gc * IN_DIM + k0 + kq * 4];
            Bs[kq * 4 + 0][row] = vb.x;
            Bs[kq * 4 + 1][row] = vb.y;
            Bs[kq * 4 + 2][row] = vb.z;
            Bs[kq * 4 + 3][row] = vb.w;
        }
        __syncthreads();

        #pragma unroll
        for (int k = 0; k < BK; k++) {
            float4 a0 = *(const float4*)&As[k][ty * 4];
            float4 a1 = *(const float4*)&As[k][64 + ty * 4];
            float4 b0 = *(const float4*)&Bs[k][tx * 4];
            float4 b1 = *(const float4*)&Bs[k][64 + tx * 4];

            unsigned long long ap[4], bp[8];
            asm("mov.b64 %0, {%1,%2};" : "=l"(ap[0]) : "f"(a0.x), "f"(a0.y));
            asm("mov.b64 %0, {%1,%2};" : "=l"(ap[1]) : "f"(a0.z), "f"(a0.w));
            asm("mov.b64 %0, {%1,%2};" : "=l"(ap[2]) : "f"(a1.x), "f"(a1.y));
            asm("mov.b64 %0, {%1,%2};" : "=l"(ap[3]) : "f"(a1.z), "f"(a1.w));
            asm("mov.b64 %0, {%1,%1};" : "=l"(bp[0]) : "f"(b0.x));
            asm("mov.b64 %0, {%1,%1};" : "=l"(bp[1]) : "f"(b0.y));
            asm("mov.b64 %0, {%1,%1};" : "=l"(bp[2]) : "f"(b0.z));
            asm("mov.b64 %0, {%1,%1};" : "=l"(bp[3]) : "f"(b0.w));
            asm("mov.b64 %0, {%1,%1};" : "=l"(bp[4]) : "f"(b1.x));
            asm("mov.b64 %0, {%1,%1};" : "=l"(bp[5]) : "f"(b1.y));
            asm("mov.b64 %0, {%1,%1};" : "=l"(bp[6]) : "f"(b1.z));
            asm("mov.b64 %0, {%1,%1};" : "=l"(bp[7]) : "f"(b1.w));

            #pragma unroll
            for (int p = 0; p < 4; p++)
                #pragma unroll
                for (int j = 0; j < 8; j++)
                    asm("fma.rn.f32x2 %0, %1, %2, %0;"
                        : "+l"(acc[p][j]) : "l"(ap[p]), "l"(bp[j]));
        }
        __syncthreads();
    }

    int c0 = colBase + tx * 4;
    int c1 = colBase + 64 + tx * 4;
    float4 bb0 = *(const float4*)&bia[c0];
    float4 bb1 = *(const float4*)&bia[c1];

    #pragma unroll
    for (int p = 0; p < 4; p++) {
        int rbase = rowBase + ((p < 2) ? (ty * 4) : (64 + ty * 4)) + (p & 1) * 2;
        float lo[8], hi[8];
        #pragma unroll
        for (int j = 0; j < 8; j++)
            asm("mov.b64 {%0,%1}, %2;" : "=f"(lo[j]), "=f"(hi[j]) : "l"(acc[p][j]));

        if (rbase < N_NODES) {
            float4 o0 = make_float4(fmaxf(lo[0] + bb0.x, 0.f), fmaxf(lo[1] + bb0.y, 0.f),
                                    fmaxf(lo[2] + bb0.z, 0.f), fmaxf(lo[3] + bb0.w, 0.f));
            float4 o1 = make_float4(fmaxf(lo[4] + bb1.x, 0.f), fmaxf(lo[5] + bb1.y, 0.f),
                                    fmaxf(lo[6] + bb1.z, 0.f), fmaxf(lo[7] + bb1.w, 0.f));
            *(float4*)&out[(size_t)rbase * OUT_DIM + c0] = o0;
            *(float4*)&out[(size_t)rbase * OUT_DIM + c1] = o1;
        }
        if (rbase + 1 < N_NODES) {
            float4 o0 = make_float4(fmaxf(hi[0] + bb0.x, 0.f), fmaxf(hi[1] + bb0.y, 0.f),
                                    fmaxf(hi[2] + bb0.z, 0.f), fmaxf(hi[3] + bb0.w, 0.f));
            float4 o1 = make_float4(fmaxf(hi[4] + bb1.x, 0.f), fmaxf(hi[5] + bb1.y, 0.f),
                                    fmaxf(hi[6] + bb1.z, 0.f), fmaxf(hi[7] + bb1.w, 0.f));
            *(float4*)&out[(size_t)(rbase + 1) * OUT_DIM + c0] = o0;
            *(float4*)&out[(size_t)(rbase + 1) * OUT_DIM + c1] = o1;
        }
    }
}

// ---------------------------------------------------------------------------
extern "C" void kernel_launch(void* const* d_in, const int* in_sizes, int n_in,
                              void* d_out, int out_size) {
    const float* x   = (const float*)d_in[0];
    const void*  ei  = d_in[1];
    const float* W   = (const float*)d_in[2];
    const float* b   = (const float*)d_in[3];
    float*       out = (float*)d_out;

    k_init <<<(N_NODES + 255) / 256, 256>>>((const long long*)ei);
    k_count<<<(N_EDGES + 255) / 256, 256>>>(ei);
    k_scanA<<<NBLK_SCAN, SCAN_BLK>>>();
    k_fill <<<(N_EDGES + 255) / 256, 256>>>(ei);

    k_gather<<<(N_NODES * 32 + 255) / 256, 256>>>(x);

    dim3 ggrid((N_NODES + BM - 1) / BM, OUT_DIM / BM);
    k_gemm<<<ggrid, 256>>>(W, b, out);
}

// round 8
// speedup vs baseline: 2.4419x; 1.3433x over previous
#include <cuda_runtime.h>
#include <cuda_bf16.h>
#include <cstdint>

#define N_NODES 50000
#define IN_DIM  128
#define OUT_DIM 256
#define N_EDGES 800000
#define SCAN_BLK 256
#define NBLK_SCAN ((N_NODES + SCAN_BLK - 1) / SCAN_BLK)

// Scratch (__device__ globals; allocation APIs are forbidden)
__device__ __nv_bfloat16 g_ahi[(size_t)N_NODES * IN_DIM];   // 12.8 MB
__device__ __nv_bfloat16 g_alo[(size_t)N_NODES * IN_DIM];   // 12.8 MB
__device__ __nv_bfloat16 g_whi[OUT_DIM * IN_DIM];
__device__ __nv_bfloat16 g_wlo[OUT_DIM * IN_DIM];
__device__ float g_dinv[N_NODES];
__device__ int   g_cnt[N_NODES];
__device__ int   g_off[N_NODES];
__device__ int   g_cur[N_NODES];
__device__ int   g_csr[N_EDGES];
__device__ int   g_total;
__device__ int   g_is32;

__device__ __forceinline__ int clamp_node(int v) {
    v = v < 0 ? 0 : v;
    return v > (N_NODES - 1) ? (N_NODES - 1) : v;
}

__device__ __forceinline__ void load_edge(const void* __restrict__ ei, int e,
                                          int& s, int& d) {
    if (g_is32) {
        const int* p = (const int*)ei;
        s = p[2 * e];
        d = p[2 * e + 1];
    } else {
        const long long* p = (const long long*)ei;
        s = (int)p[2 * e];
        d = (int)p[2 * e + 1];
    }
    s = clamp_node(s);
    d = clamp_node(d);
}

__device__ __forceinline__ uint32_t smem_u32(const void* p) {
    uint32_t a;
    asm("{ .reg .u64 t; cvta.to.shared.u64 t, %1; cvt.u32.u64 %0, t; }"
        : "=r"(a) : "l"(p));
    return a;
}

__device__ __forceinline__ void ldm_x4(uint32_t addr, uint32_t& r0, uint32_t& r1,
                                       uint32_t& r2, uint32_t& r3) {
    asm volatile("ldmatrix.sync.aligned.m8n8.x4.shared.b16 {%0,%1,%2,%3}, [%4];"
                 : "=r"(r0), "=r"(r1), "=r"(r2), "=r"(r3) : "r"(addr));
}

__device__ __forceinline__ void ldm_x2(uint32_t addr, uint32_t& r0, uint32_t& r1) {
    asm volatile("ldmatrix.sync.aligned.m8n8.x2.shared.b16 {%0,%1}, [%2];"
                 : "=r"(r0), "=r"(r1) : "r"(addr));
}

__device__ __forceinline__ void mma_bf16(float* c, const uint32_t* a,
                                         const uint32_t* b) {
    asm volatile(
        "mma.sync.aligned.m16n8k16.row.col.f32.bf16.bf16.f32 "
        "{%0,%1,%2,%3}, {%4,%5,%6,%7}, {%8,%9}, {%0,%1,%2,%3};"
        : "+f"(c[0]), "+f"(c[1]), "+f"(c[2]), "+f"(c[3])
        : "r"(a[0]), "r"(a[1]), "r"(a[2]), "r"(a[3]), "r"(b[0]), "r"(b[1]));
}

// ---------------------------------------------------------------------------
// init: zero counters + cursor; block 0 probes int32-vs-int64 edge encoding.
// ---------------------------------------------------------------------------
__global__ void k_init(const long long* __restrict__ ei) {
    int i = blockIdx.x * blockDim.x + threadIdx.x;
    if (i < N_NODES) g_cnt[i] = 0;
    if (i == 0) g_total = 0;
    if (blockIdx.x == 0) {
        __shared__ int bad[256];
        int t = threadIdx.x;
        int local = 0;
        for (int k = t; k < 1024; k += 256) {
            long long v = ei[k];
            if (v < 0 || v >= (long long)N_NODES) local = 1;
        }
        bad[t] = local;
        __syncthreads();
        for (int off = 128; off > 0; off >>= 1) {
            if (t < off) bad[t] |= bad[t + off];
            __syncthreads();
        }
        if (t == 0) g_is32 = bad[0];
    }
}

__global__ void k_count(const void* __restrict__ ei) {
    int e = blockIdx.x * blockDim.x + threadIdx.x;
    if (e < N_EDGES) {
        int s, d;
        load_edge(ei, e, s, d);
        atomicAdd(&g_cnt[d], 1);
    }
}

// One-kernel offsets: block-local scan + atomic block base (order-free CSR).
__global__ void k_scanA() {
    __shared__ int sh[SCAN_BLK];
    __shared__ int blockBase;
    int t = threadIdx.x;
    int i = blockIdx.x * SCAN_BLK + t;
    int v = (i < N_NODES) ? g_cnt[i] : 0;
    sh[t] = v;
    __syncthreads();
    for (int off = 1; off < SCAN_BLK; off <<= 1) {
        int add = (t >= off) ? sh[t - off] : 0;
        __syncthreads();
        sh[t] += add;
        __syncthreads();
    }
    if (t == SCAN_BLK - 1) blockBase = atomicAdd(&g_total, sh[SCAN_BLK - 1]);
    __syncthreads();
    if (i < N_NODES) {
        int o = blockBase + sh[t] - v;
        g_off[i] = o;
        g_cur[i] = o;
        g_dinv[i] = rsqrtf((float)(v + 1));   // +1 self loop
    }
}

__global__ void k_fill(const void* __restrict__ ei) {
    int e = blockIdx.x * blockDim.x + threadIdx.x;
    if (e < N_EDGES) {
        int s, d;
        load_edge(ei, e, s, d);
        int pos = atomicAdd(&g_cur[d], 1);
        pos = pos < 0 ? 0 : (pos > N_EDGES - 1 ? N_EDGES - 1 : pos);
        g_csr[pos] = s;
    }
}

// W split: whi = bf16(W), wlo = bf16(W - whi)
__global__ void k_wconv(const float* __restrict__ W) {
    int i = blockIdx.x * blockDim.x + threadIdx.x;
    if (i < OUT_DIM * IN_DIM) {
        float v = W[i];
        __nv_bfloat16 h = __float2bfloat16(v);
        g_whi[i] = h;
        g_wlo[i] = __float2bfloat16(v - __bfloat162float(h));
    }
}

// ---------------------------------------------------------------------------
// Gather: agg[d] = dinv[d]*(dinv[d]*x[d] + sum dinv[s]*x[s]); emits bf16 hi/lo.
// One warp per node; lane owns 4 feature columns.
// ---------------------------------------------------------------------------
__global__ __launch_bounds__(256) void k_gather(const float* __restrict__ x) {
    int d    = (blockIdx.x * blockDim.x + threadIdx.x) >> 5;
    int lane = threadIdx.x & 31;
    if (d >= N_NODES) return;

    const float4* xr = (const float4*)x;
    float dd = g_dinv[d];
    float4 v = xr[(size_t)d * 32 + lane];
    float4 acc = make_float4(dd * v.x, dd * v.y, dd * v.z, dd * v.w);

    int e   = g_off[d];
    int end = e + g_cnt[d];

    for (; e + 4 <= end; e += 4) {
        int s0 = g_csr[e + 0], s1 = g_csr[e + 1];
        int s2 = g_csr[e + 2], s3 = g_csr[e + 3];
        float w0 = g_dinv[s0], w1 = g_dinv[s1];
        float w2 = g_dinv[s2], w3 = g_dinv[s3];
        float4 x0 = xr[(size_t)s0 * 32 + lane];
        float4 x1 = xr[(size_t)s1 * 32 + lane];
        float4 x2 = xr[(size_t)s2 * 32 + lane];
        float4 x3 = xr[(size_t)s3 * 32 + lane];
        acc.x += w0 * x0.x; acc.y += w0 * x0.y; acc.z += w0 * x0.z; acc.w += w0 * x0.w;
        acc.x += w1 * x1.x; acc.y += w1 * x1.y; acc.z += w1 * x1.z; acc.w += w1 * x1.w;
        acc.x += w2 * x2.x; acc.y += w2 * x2.y; acc.z += w2 * x2.z; acc.w += w2 * x2.w;
        acc.x += w3 * x3.x; acc.y += w3 * x3.y; acc.z += w3 * x3.z; acc.w += w3 * x3.w;
    }
    for (; e < end; e++) {
        int   s = g_csr[e];
        float w = g_dinv[s];
        float4 xv = xr[(size_t)s * 32 + lane];
        acc.x += w * xv.x; acc.y += w * xv.y; acc.z += w * xv.z; acc.w += w * xv.w;
    }

    acc.x *= dd; acc.y *= dd; acc.z *= dd; acc.w *= dd;

    __nv_bfloat162 h01 = __floats2bfloat162_rn(acc.x, acc.y);
    __nv_bfloat162 h23 = __floats2bfloat162_rn(acc.z, acc.w);
    __nv_bfloat162 l01 = __floats2bfloat162_rn(acc.x - __bfloat162float(h01.x),
                                               acc.y - __bfloat162float(h01.y));
    __nv_bfloat162 l23 = __floats2bfloat162_rn(acc.z - __bfloat162float(h23.x),
                                               acc.w - __bfloat162float(h23.y));
    __nv_bfloat162* ah = (__nv_bfloat162*)g_ahi;
    __nv_bfloat162* al = (__nv_bfloat162*)g_alo;
    size_t base = (size_t)d * 64 + lane * 2;
    ah[base] = h01; ah[base + 1] = h23;
    al[base] = l01; al[base + 1] = l23;
}

// ---------------------------------------------------------------------------
// HMMA GEMM: out = relu((Ahi+Alo) @ (Whi+Wlo)^T + b), dropping lo*lo.
// CTA tile 128x128, whole K=128 staged in smem. 8 warps, 64x32 warp tiles.
// mma.sync.m16n8k16.bf16 with fp32 accumulate; ldmatrix feeds fragments.
// Tiles padded to stride 272B -> ldmatrix phases conflict-free.
// ---------------------------------------------------------------------------
#define GSB 272                 // smem row stride in bytes (136 bf16)
#define TILE_B (128 * GSB)      // 34816 bytes per plane
#define SM_AHI 0
#define SM_ALO (SM_AHI + TILE_B)
#define SM_BHI (SM_ALO + TILE_B)
#define SM_BLO (SM_BHI + TILE_B)
#define SM_TOTAL (SM_BLO + TILE_B)   // 139264 bytes

__device__ __forceinline__ void stage_tile(char* smem, int smoff,
        const __nv_bfloat16* __restrict__ g, int rowBase, int rowMax, int tid) {
    #pragma unroll
    for (int it = 0; it < 8; it++) {        // 128 rows x 16 chunks / 256 thr
        int idx = tid + it * 256;
        int row = idx >> 4;                 // 0..127
        int c   = idx & 15;                 // 16B chunk (8 bf16)
        int gr  = rowBase + row;
        int4 v = make_int4(0, 0, 0, 0);
        if (gr < rowMax) v = *(const int4*)&g[(size_t)gr * IN_DIM + c * 8];
        *(int4*)(smem + smoff + row * GSB + c * 16) = v;
    }
}

__global__ __launch_bounds__(256, 1)
void k_gemm_mma(const float* __restrict__ bia, float* __restrict__ out) {
    extern __shared__ char smem[];
    const int tid  = threadIdx.x;
    const int wid  = tid >> 5;
    const int lane = tid & 31;
    const int warp_m = wid >> 2;            // 0..1  (64-row slab)
    const int warp_n = wid & 3;             // 0..3  (32-col slab)
    const int rowBase = blockIdx.x * 128;
    const int colBase = blockIdx.y * 128;

    stage_tile(smem, SM_AHI, g_ahi, rowBase, N_NODES, tid);
    stage_tile(smem, SM_ALO, g_alo, rowBase, N_NODES, tid);
    stage_tile(smem, SM_BHI, g_whi, colBase, OUT_DIM, tid);
    stage_tile(smem, SM_BLO, g_wlo, colBase, OUT_DIM, tid);
    __syncthreads();

    uint32_t smb = smem_u32(smem);

    // ldmatrix per-lane address components
    // A (x4): lanes 0-7 -> m0-7/klow, 8-15 -> m8-15/klow, 16-23 -> m0-7/khi,
    //         24-31 -> m8-15/khi
    uint32_t aRow   = warp_m * 64 + (lane & 15);
    uint32_t aChunk = (lane >> 4) * 16;               // 0 or 16 bytes
    uint32_t aOff   = aRow * GSB + aChunk;
    // B (x2): lanes 0-7 -> n-rows/klow, 8-15 -> n-rows/khigh
    uint32_t bRow   = warp_n * 32 + (lane & 7);
    uint32_t bChunk = ((lane >> 3) & 1) * 16;
    uint32_t bOff   = bRow * GSB + bChunk;

    float acc[4][4][4];
    #pragma unroll
    for (int i = 0; i < 4; i++)
        #pragma unroll
        for (int j = 0; j < 4; j++)
            #pragma unroll
            for (int q = 0; q < 4; q++) acc[i][j][q] = 0.f;

    #pragma unroll
    for (int ks = 0; ks < 8; ks++) {                  // k16 steps
        uint32_t kByte = ks * 32;                     // 16 bf16 = 32 B

        uint32_t bh[4][2], bl[4][2];
        #pragma unroll
        for (int j = 0; j < 4; j++) {
            uint32_t ba = bOff + j * 8 * GSB + kByte;
            ldm_x2(smb + SM_BHI + ba, bh[j][0], bh[j][1]);
            ldm_x2(smb + SM_BLO + ba, bl[j][0], bl[j][1]);
        }

        #pragma unroll
        for (int i = 0; i < 4; i++) {
            uint32_t aa = aOff + i * 16 * GSB + kByte;
            uint32_t ah[4], al[4];
            ldm_x4(smb + SM_AHI + aa, ah[0], ah[1], ah[2], ah[3]);
            ldm_x4(smb + SM_ALO + aa, al[0], al[1], al[2], al[3]);
            #pragma unroll
            for (int j = 0; j < 4; j++) {
                mma_bf16(acc[i][j], ah, bh[j]);   // hi*hi
                mma_bf16(acc[i][j], ah, bl[j]);   // hi*lo
                mma_bf16(acc[i][j], al, bh[j]);   // lo*hi
            }
        }
    }

    // Epilogue: c frag m16n8: lane -> (row=lane/4 [+8], col=(lane%4)*2 [+1])
    #pragma unroll
    for (int i = 0; i < 4; i++) {
        int r = rowBase + warp_m * 64 + i * 16 + (lane >> 2);
        #pragma unroll
        for (int j = 0; j < 4; j++) {
            int cb = colBase + warp_n * 32 + j * 8 + (lane & 3) * 2;
            float b0 = bia[cb], b1 = bia[cb + 1];
            if (r < N_NODES) {
                float2 o;
                o.x = fmaxf(acc[i][j][0] + b0, 0.f);
                o.y = fmaxf(acc[i][j][1] + b1, 0.f);
                *(float2*)&out[(size_t)r * OUT_DIM + cb] = o;
            }
            if (r + 8 < N_NODES) {
                float2 o;
                o.x = fmaxf(acc[i][j][2] + b0, 0.f);
                o.y = fmaxf(acc[i][j][3] + b1, 0.f);
                *(float2*)&out[(size_t)(r + 8) * OUT_DIM + cb] = o;
            }
        }
    }
}

// ---------------------------------------------------------------------------
extern "C" void kernel_launch(void* const* d_in, const int* in_sizes, int n_in,
                              void* d_out, int out_size) {
    const float* x   = (const float*)d_in[0];
    const void*  ei  = d_in[1];
    const float* W   = (const float*)d_in[2];
    const float* b   = (const float*)d_in[3];
    float*       out = (float*)d_out;

    cudaFuncSetAttribute(k_gemm_mma, cudaFuncAttributeMaxDynamicSharedMemorySize,
                         SM_TOTAL);

    k_init <<<(N_NODES + 255) / 256, 256>>>((const long long*)ei);
    k_count<<<(N_EDGES + 255) / 256, 256>>>(ei);
    k_scanA<<<NBLK_SCAN, SCAN_BLK>>>();
    k_fill <<<(N_EDGES + 255) / 256, 256>>>(ei);
    k_wconv<<<(OUT_DIM * IN_DIM + 255) / 256, 256>>>(W);

    k_gather<<<(N_NODES * 32 + 255) / 256, 256>>>(x);

    dim3 ggrid((N_NODES + 127) / 128, OUT_DIM / 128);
    k_gemm_mma<<<ggrid, 256, SM_TOTAL>>>(b, out);
}